// round 13
// baseline (speedup 1.0000x reference)
#include <cuda_runtime.h>
#include <cuda_fp16.h>
#include <cstdint>

// Grouped GEMM via fp16 2-term split on mma.sync (base sm_103 target).
// C = Ahi@Bh^T + Alo@Bh^T, A = Ahi + Alo (fp16), Bh = fp16(B).
// R13: warp-specialized, 640 threads = 16 consumer warps (32x32 tiles) +
//      4 producer warps. 1 CTA/SM, 4-stage BK=64 mbarrier pipeline,
//      persistent work-stealing.

constexpr int M_DIM = 8192;
constexpr int K_DIM = 1024;
constexpr int N_DIM = 1024;
constexpr int E_SEG = 8;

#define BM 128
#define BN 128
#define BK 64
#define THREADS 640
constexpr int KT = K_DIM / BK;               // 16 k-chunks
constexpr int MAT_BYTES = 128 * 128;         // 16384: 128 rows x 128B (64 fp16)
constexpr int STAGE_BYTES = 3 * MAT_BYTES;   // Ahi, Alo, Bh = 49152
constexpr int NSTAGE = 4;
constexpr int MBAR_OFF = NSTAGE * STAGE_BYTES;   // 196608
constexpr int SMEM_TOTAL = MBAR_OFF + 128;       // <= 227KB
constexpr int NTILES = (M_DIM / BM) * (N_DIM / BN);  // 512
constexpr int GRID_P = 148;                  // 1 CTA/SM

// Split storage (fp16)
__device__ __half g_Ahi[(size_t)M_DIM * K_DIM];
__device__ __half g_Alo[(size_t)M_DIM * K_DIM];
__device__ __half g_Bh [(size_t)E_SEG * N_DIM * K_DIM];
__device__ unsigned g_tileCtr;

constexpr int NA4 = (M_DIM * K_DIM) / 4;
constexpr int NB4 = (E_SEG * N_DIM * K_DIM) / 4;

// ---------------- prepass (also resets the tile counter) ----------------
__global__ void __launch_bounds__(256)
split_AB(const float4* __restrict__ A, const float4* __restrict__ B) {
    if (blockIdx.x == 0 && threadIdx.x == 0) g_tileCtr = 0u;  // ordered by kernel
    size_t i = (size_t)blockIdx.x * 256 + threadIdx.x;        // boundary vs GEMM
    if (i < (size_t)NA4) {
        float4 v = A[i];
        __half h0 = __float2half(v.x), h1 = __float2half(v.y);
        __half h2 = __float2half(v.z), h3 = __float2half(v.w);
        __half l0 = __float2half(v.x - __half2float(h0));
        __half l1 = __float2half(v.y - __half2float(h1));
        __half l2 = __float2half(v.z - __half2float(h2));
        __half l3 = __float2half(v.w - __half2float(h3));
        ((ushort4*)g_Ahi)[i] = make_ushort4(__half_as_ushort(h0), __half_as_ushort(h1),
                                            __half_as_ushort(h2), __half_as_ushort(h3));
        ((ushort4*)g_Alo)[i] = make_ushort4(__half_as_ushort(l0), __half_as_ushort(l1),
                                            __half_as_ushort(l2), __half_as_ushort(l3));
    } else {
        size_t j = i - NA4;
        float4 v = B[j];
        ((ushort4*)g_Bh)[j] = make_ushort4(
            __half_as_ushort(__float2half(v.x)), __half_as_ushort(__float2half(v.y)),
            __half_as_ushort(__float2half(v.z)), __half_as_ushort(__float2half(v.w)));
    }
}

// ---------------- asm helpers ----------------
__device__ __forceinline__ void cp16(uint32_t dst, const void* src) {
    asm volatile("cp.async.cg.shared.global [%0], [%1], 16;" :: "r"(dst), "l"(src));
}
__device__ __forceinline__ void ldsm4(uint32_t addr, uint32_t r[4]) {
    asm volatile("ldmatrix.sync.aligned.m8n8.x4.shared.b16 {%0,%1,%2,%3}, [%4];"
                 : "=r"(r[0]), "=r"(r[1]), "=r"(r[2]), "=r"(r[3]) : "r"(addr));
}
__device__ __forceinline__ void mma16816(float d[4], const uint32_t a[4],
                                         uint32_t b0, uint32_t b1) {
    asm volatile(
        "mma.sync.aligned.m16n8k16.row.col.f32.f16.f16.f32 "
        "{%0,%1,%2,%3}, {%4,%5,%6,%7}, {%8,%9}, {%0,%1,%2,%3};"
        : "+f"(d[0]), "+f"(d[1]), "+f"(d[2]), "+f"(d[3])
        : "r"(a[0]), "r"(a[1]), "r"(a[2]), "r"(a[3]), "r"(b0), "r"(b1));
}
__device__ __forceinline__ void mbar_init(uint32_t m, uint32_t cnt) {
    asm volatile("mbarrier.init.shared.b64 [%0], %1;" :: "r"(m), "r"(cnt) : "memory");
}
__device__ __forceinline__ void mbar_arrive(uint32_t m) {
    asm volatile("mbarrier.arrive.shared.b64 _, [%0];" :: "r"(m) : "memory");
}
__device__ __forceinline__ void cpasync_arrive(uint32_t m) {
    asm volatile("cp.async.mbarrier.arrive.noinc.shared.b64 [%0];" :: "r"(m) : "memory");
}
__device__ __forceinline__ void mbar_wait(uint32_t m, uint32_t parity) {
    uint32_t done;
    asm volatile("{\n\t.reg .pred p;\n\t"
                 "mbarrier.try_wait.parity.acquire.cta.shared::cta.b64 p, [%1], %2;\n\t"
                 "selp.b32 %0, 1, 0, p;\n\t}" : "=r"(done) : "r"(m), "r"(parity) : "memory");
    if (!done) {
        asm volatile("{\n\t.reg .pred P1;\n\t"
                     "W_%=:\n\t"
                     "mbarrier.try_wait.parity.acquire.cta.shared::cta.b64 P1, [%0], %1, 0x989680;\n\t"
                     "@P1 bra.uni D_%=;\n\t"
                     "bra.uni W_%=;\n\t"
                     "D_%=:\n\t}" :: "r"(m), "r"(parity) : "memory");
    }
}

// 128B-row SW128 swizzle: XOR chunk bits[6:4] with row bits[2:0].
__device__ __forceinline__ uint32_t swz(uint32_t row, uint32_t colB) {
    return row * 128u + (colB ^ ((row & 7u) << 4));
}

// ---------------- main kernel ----------------
__global__ void __launch_bounds__(THREADS, 1)
grouped_gemm_hmma(const int* __restrict__ seg_indptr,
                  const int* __restrict__ widx,
                  float* __restrict__ C)
{
    extern __shared__ char smem[];
    const uint32_t sb = (uint32_t)__cvta_generic_to_shared(smem);
    const int tid = threadIdx.x;
    const int wid = tid >> 5;
    const int lane = tid & 31;

    const uint32_t mbF = sb + MBAR_OFF;        // full[i]  at +8*i (4 stages)
    const uint32_t mbE = sb + MBAR_OFF + 32;   // empty[i] at +8*i
    volatile unsigned* sTile = (volatile unsigned*)(smem + MBAR_OFF + 64);

    if (tid == 0) {
        #pragma unroll
        for (int i = 0; i < NSTAGE; ++i) {
            mbar_init(mbF + i * 8, 128);   // one .noinc arrival per producer thread
            mbar_init(mbE + i * 8, 16);    // one arrival per consumer warp
        }
    }
    __syncthreads();

    // consumer warp layout (wid 0..15): 32x32 tiles in a 4x4 grid
    const int warp_m = wid >> 2;            // 0..3 -> row offset *32
    const int warp_n = wid & 3;             // 0..3 -> col offset *32
    const uint32_t aRow = (uint32_t)(warp_m * 32 + (lane & 15));
    const uint32_t bRow = (uint32_t)(warp_n * 32 + (lane & 7) + ((lane >> 4) & 1) * 8);
    const uint32_t aSel = (uint32_t)((lane >> 4) * 16);
    const uint32_t bSel = (uint32_t)(((lane >> 3) & 1) * 16);

    // producer thread layout (tid 512..639): 1024 chunks/matrix, 8 per thread
    const int pt = tid - 512;                       // 0..127 (producers only)
    const uint32_t ldR = (uint32_t)(pt >> 3);       // rows 0..15 (+16 per blk)
    const uint32_t ldC = (uint32_t)(pt & 7);        // chunk 0..7 in row

    int pst = 0, pph = 1;   // producer cursor
    int cst = 0, cph = 0;   // consumer cursor

    #pragma unroll 1
    for (;;) {
        __syncthreads();                       // prior tile fully drained
        if (tid == 0) *sTile = atomicAdd(&g_tileCtr, 1u);
        __syncthreads();
        const unsigned t = *sTile;
        if (t >= (unsigned)NTILES) break;

        const int row0 = (int)(t >> 3) * BM;
        const int col0 = (int)(t & 7) * BN;

        // enumerate items (segments intersecting this row band) — all threads
        int nIt = 0;
        int iRlo[E_SEG], iRhi[E_SEG];
        const __half* iB[E_SEG];
        #pragma unroll 1
        for (int s = 0; s < E_SEG; ++s) {
            const int rlo = max(seg_indptr[s], row0);
            const int rhi = min(seg_indptr[s + 1], row0 + BM);
            if (rlo < rhi) {
                iRlo[nIt] = rlo; iRhi[nIt] = rhi;
                iB[nIt] = g_Bh + (size_t)widx[s] * ((size_t)N_DIM * K_DIM);
                ++nIt;
            }
        }
        const int total = nIt * KT;

        if (wid >= 16) {
            // ================= PRODUCER WARPS =================
            #pragma unroll 1
            for (int q = 0; q < total; ++q) {
                const int it = q >> 4;
                const int kt = q & 15;
                mbar_wait(mbE + pst * 8, (uint32_t)pph);
                const uint32_t stg = sb + pst * STAGE_BYTES;
                const int ke = kt * BK + (int)ldC * 8;
                const __half* __restrict__ be = iB[it];
                #pragma unroll
                for (int blk = 0; blk < 8; ++blk) {
                    const uint32_t r = ldR + blk * 16;
                    const uint32_t so = swz(r, ldC * 16);
                    cp16(stg + so,                 g_Ahi + (size_t)(row0 + r) * K_DIM + ke);
                    cp16(stg + MAT_BYTES + so,     g_Alo + (size_t)(row0 + r) * K_DIM + ke);
                    cp16(stg + 2 * MAT_BYTES + so, be + (size_t)(col0 + r) * K_DIM + ke);
                }
                cpasync_arrive(mbF + pst * 8);
                if (++pst == NSTAGE) { pst = 0; pph ^= 1; }
            }
        } else {
            // ================= CONSUMER WARPS =================
            float acc[2][4][4];
            #pragma unroll
            for (int i = 0; i < 2; ++i)
                #pragma unroll
                for (int j = 0; j < 4; ++j)
                    #pragma unroll
                    for (int p = 0; p < 4; ++p) acc[i][j][p] = 0.f;

            #pragma unroll 1
            for (int q = 0; q < total; ++q) {
                mbar_wait(mbF + cst * 8, (uint32_t)cph);

                const uint32_t stg    = sb + cst * STAGE_BYTES;
                const uint32_t stgAhi = stg;
                const uint32_t stgAlo = stg + MAT_BYTES;
                const uint32_t stgBh  = stg + 2 * MAT_BYTES;

                #pragma unroll
                for (int kh = 0; kh < 4; ++kh) {
                    const uint32_t aCB = (uint32_t)(kh * 32) + aSel;
                    const uint32_t bCB = (uint32_t)(kh * 32) + bSel;

                    uint32_t ah[2][4], bh[2][4];
                    #pragma unroll
                    for (int mt = 0; mt < 2; ++mt)
                        ldsm4(stgAhi + swz(aRow + mt * 16, aCB), ah[mt]);
                    #pragma unroll
                    for (int p = 0; p < 2; ++p)
                        ldsm4(stgBh + swz(bRow + p * 16, bCB), bh[p]);

                    #pragma unroll
                    for (int mt = 0; mt < 2; ++mt)
                        #pragma unroll
                        for (int nt = 0; nt < 4; ++nt)
                            mma16816(acc[mt][nt], ah[mt],
                                     bh[nt >> 1][(nt & 1) * 2], bh[nt >> 1][(nt & 1) * 2 + 1]);

                    uint32_t al[2][4];
                    #pragma unroll
                    for (int mt = 0; mt < 2; ++mt)
                        ldsm4(stgAlo + swz(aRow + mt * 16, aCB), al[mt]);

                    #pragma unroll
                    for (int mt = 0; mt < 2; ++mt)
                        #pragma unroll
                        for (int nt = 0; nt < 4; ++nt)
                            mma16816(acc[mt][nt], al[mt],
                                     bh[nt >> 1][(nt & 1) * 2], bh[nt >> 1][(nt & 1) * 2 + 1]);
                }

                if (lane == 0) mbar_arrive(mbE + cst * 8);
                if (++cst == NSTAGE) { cst = 0; cph ^= 1; }

                // item boundary -> epilogue + acc reset (producers keep filling)
                if ((q & 15) == 15) {
                    const int it = q >> 4;
                    const int rloI = iRlo[it], rhiI = iRhi[it];
                    const int cbase = col0 + warp_n * 32 + (lane & 3) * 2;
                    #pragma unroll
                    for (int mt = 0; mt < 2; ++mt) {
                        const int r0 = row0 + warp_m * 32 + mt * 16 + (lane >> 2);
                        const int r1 = r0 + 8;
                        const bool w0 = (r0 >= rloI && r0 < rhiI);
                        const bool w1 = (r1 >= rloI && r1 < rhiI);
                        #pragma unroll
                        for (int nt = 0; nt < 4; ++nt) {
                            const int cc = cbase + nt * 8;
                            if (w0) *(float2*)&C[(size_t)r0 * N_DIM + cc] =
                                        make_float2(acc[mt][nt][0], acc[mt][nt][1]);
                            if (w1) *(float2*)&C[(size_t)r1 * N_DIM + cc] =
                                        make_float2(acc[mt][nt][2], acc[mt][nt][3]);
                        }
                    }
                    #pragma unroll
                    for (int i = 0; i < 2; ++i)
                        #pragma unroll
                        for (int j = 0; j < 4; ++j)
                            #pragma unroll
                            for (int p = 0; p < 4; ++p) acc[i][j][p] = 0.f;
                }
            }
        }
    }
}

extern "C" void kernel_launch(void* const* d_in, const int* in_sizes, int n_in,
                              void* d_out, int out_size)
{
    const float* a = (const float*)d_in[0];    // [M, K]
    const float* b = (const float*)d_in[1];    // [E, N, K]
    const int* seg = nullptr;
    const int* widx = nullptr;
    for (int i = 0; i < n_in; ++i) {
        if (in_sizes[i] == E_SEG + 1)  seg  = (const int*)d_in[i];
        else if (in_sizes[i] == E_SEG) widx = (const int*)d_in[i];
    }
    float* c = (float*)d_out;

    split_AB<<<(NA4 + NB4) / 256, 256>>>((const float4*)a, (const float4*)b);

    cudaFuncSetAttribute(grouped_gemm_hmma,
                         cudaFuncAttributeMaxDynamicSharedMemorySize, SMEM_TOTAL);
    grouped_gemm_hmma<<<GRID_P, THREADS, SMEM_TOTAL>>>(seg, widx, c);
}

// round 14
// speedup vs baseline: 1.2031x; 1.2031x over previous
#include <cuda_runtime.h>
#include <cuda_fp16.h>
#include <cstdint>

// Grouped GEMM via fp16 2-term split on mma.sync (base sm_103 target).
// C = Ahi@Bh^T + Alo@Bh^T, A = Ahi + Alo (fp16), Bh = fp16(B).
// R14: R12 geometry (8 consumer warps 64x32 + 4 producer warps, 1 CTA/SM,
//      4-stage BK=64) + item-granular work stealing (equal 16-kt units via
//      per-band prefix table) + kh phase skew for consumer decorrelation.

constexpr int M_DIM = 8192;
constexpr int K_DIM = 1024;
constexpr int N_DIM = 1024;
constexpr int E_SEG = 8;

#define BM 128
#define BN 128
#define BK 64
#define THREADS 384
constexpr int KT = K_DIM / BK;               // 16 k-chunks per unit
constexpr int MAT_BYTES = 128 * 128;         // 16384: 128 rows x 128B (64 fp16)
constexpr int STAGE_BYTES = 3 * MAT_BYTES;   // Ahi, Alo, Bh = 49152
constexpr int NSTAGE = 4;
constexpr int MBAR_OFF = NSTAGE * STAGE_BYTES;   // 196608
constexpr int PREF_OFF = MBAR_OFF + 128;         // prefix table (65 ints)
constexpr int SMEM_TOTAL = PREF_OFF + 272;
constexpr int NBANDS = M_DIM / BM;           // 64
constexpr int GRID_P = 148;                  // 1 CTA/SM

// Split storage (fp16)
__device__ __half g_Ahi[(size_t)M_DIM * K_DIM];
__device__ __half g_Alo[(size_t)M_DIM * K_DIM];
__device__ __half g_Bh [(size_t)E_SEG * N_DIM * K_DIM];
__device__ unsigned g_tileCtr;

constexpr int NA4 = (M_DIM * K_DIM) / 4;
constexpr int NB4 = (E_SEG * N_DIM * K_DIM) / 4;

// ---------------- prepass (also resets the unit counter) ----------------
__global__ void __launch_bounds__(256)
split_AB(const float4* __restrict__ A, const float4* __restrict__ B) {
    if (blockIdx.x == 0 && threadIdx.x == 0) g_tileCtr = 0u;  // ordered by kernel
    size_t i = (size_t)blockIdx.x * 256 + threadIdx.x;        // boundary vs GEMM
    if (i < (size_t)NA4) {
        float4 v = A[i];
        __half h0 = __float2half(v.x), h1 = __float2half(v.y);
        __half h2 = __float2half(v.z), h3 = __float2half(v.w);
        __half l0 = __float2half(v.x - __half2float(h0));
        __half l1 = __float2half(v.y - __half2float(h1));
        __half l2 = __float2half(v.z - __half2float(h2));
        __half l3 = __float2half(v.w - __half2float(h3));
        ((ushort4*)g_Ahi)[i] = make_ushort4(__half_as_ushort(h0), __half_as_ushort(h1),
                                            __half_as_ushort(h2), __half_as_ushort(h3));
        ((ushort4*)g_Alo)[i] = make_ushort4(__half_as_ushort(l0), __half_as_ushort(l1),
                                            __half_as_ushort(l2), __half_as_ushort(l3));
    } else {
        size_t j = i - NA4;
        float4 v = B[j];
        ((ushort4*)g_Bh)[j] = make_ushort4(
            __half_as_ushort(__float2half(v.x)), __half_as_ushort(__float2half(v.y)),
            __half_as_ushort(__float2half(v.z)), __half_as_ushort(__float2half(v.w)));
    }
}

// ---------------- asm helpers ----------------
__device__ __forceinline__ void cp16(uint32_t dst, const void* src) {
    asm volatile("cp.async.cg.shared.global [%0], [%1], 16;" :: "r"(dst), "l"(src));
}
__device__ __forceinline__ void ldsm4(uint32_t addr, uint32_t r[4]) {
    asm volatile("ldmatrix.sync.aligned.m8n8.x4.shared.b16 {%0,%1,%2,%3}, [%4];"
                 : "=r"(r[0]), "=r"(r[1]), "=r"(r[2]), "=r"(r[3]) : "r"(addr));
}
__device__ __forceinline__ void mma16816(float d[4], const uint32_t a[4],
                                         uint32_t b0, uint32_t b1) {
    asm volatile(
        "mma.sync.aligned.m16n8k16.row.col.f32.f16.f16.f32 "
        "{%0,%1,%2,%3}, {%4,%5,%6,%7}, {%8,%9}, {%0,%1,%2,%3};"
        : "+f"(d[0]), "+f"(d[1]), "+f"(d[2]), "+f"(d[3])
        : "r"(a[0]), "r"(a[1]), "r"(a[2]), "r"(a[3]), "r"(b0), "r"(b1));
}
__device__ __forceinline__ void mbar_init(uint32_t m, uint32_t cnt) {
    asm volatile("mbarrier.init.shared.b64 [%0], %1;" :: "r"(m), "r"(cnt) : "memory");
}
__device__ __forceinline__ void mbar_arrive(uint32_t m) {
    asm volatile("mbarrier.arrive.shared.b64 _, [%0];" :: "r"(m) : "memory");
}
__device__ __forceinline__ void cpasync_arrive(uint32_t m) {
    asm volatile("cp.async.mbarrier.arrive.noinc.shared.b64 [%0];" :: "r"(m) : "memory");
}
__device__ __forceinline__ void mbar_wait(uint32_t m, uint32_t parity) {
    uint32_t done;
    asm volatile("{\n\t.reg .pred p;\n\t"
                 "mbarrier.try_wait.parity.acquire.cta.shared::cta.b64 p, [%1], %2;\n\t"
                 "selp.b32 %0, 1, 0, p;\n\t}" : "=r"(done) : "r"(m), "r"(parity) : "memory");
    if (!done) {
        asm volatile("{\n\t.reg .pred P1;\n\t"
                     "W_%=:\n\t"
                     "mbarrier.try_wait.parity.acquire.cta.shared::cta.b64 P1, [%0], %1, 0x989680;\n\t"
                     "@P1 bra.uni D_%=;\n\t"
                     "bra.uni W_%=;\n\t"
                     "D_%=:\n\t}" :: "r"(m), "r"(parity) : "memory");
    }
}

// 128B-row SW128 swizzle: XOR chunk bits[6:4] with row bits[2:0].
__device__ __forceinline__ uint32_t swz(uint32_t row, uint32_t colB) {
    return row * 128u + (colB ^ ((row & 7u) << 4));
}

// ---------------- main kernel ----------------
__global__ void __launch_bounds__(THREADS, 1)
grouped_gemm_hmma(const int* __restrict__ seg_indptr,
                  const int* __restrict__ widx,
                  float* __restrict__ C)
{
    extern __shared__ char smem[];
    const uint32_t sb = (uint32_t)__cvta_generic_to_shared(smem);
    const int tid = threadIdx.x;
    const int wid = tid >> 5;
    const int lane = tid & 31;

    const uint32_t mbF = sb + MBAR_OFF;        // full[i]  at +8*i (4 stages)
    const uint32_t mbE = sb + MBAR_OFF + 32;   // empty[i] at +8*i
    volatile unsigned* sTile = (volatile unsigned*)(smem + MBAR_OFF + 64);
    int* sPref = (int*)(smem + PREF_OFF);      // [0..64] unit prefix (x8 cols)

    // load segment pointers once (9 ints)
    int sv[E_SEG + 1];
    #pragma unroll
    for (int s = 0; s <= E_SEG; ++s) sv[s] = seg_indptr[s];

    if (tid == 0) {
        #pragma unroll
        for (int i = 0; i < NSTAGE; ++i) {
            mbar_init(mbF + i * 8, 128);   // one .noinc arrival per producer thread
            mbar_init(mbE + i * 8, 8);     // one arrival per consumer warp
        }
        // per-band prefix of (intersecting items) * 8 columns
        int acc = 0;
        sPref[0] = 0;
        for (int m = 0; m < NBANDS; ++m) {
            const int lo = m * BM, hi = lo + BM;
            int c = 0;
            #pragma unroll
            for (int s = 0; s < E_SEG; ++s)
                if (max(sv[s], lo) < min(sv[s + 1], hi)) ++c;
            acc += 8 * c;
            sPref[m + 1] = acc;
        }
    }
    __syncthreads();
    const int nUnits = sPref[NBANDS];

    // consumer warp layout (wid 0..7): 64x32 tiles
    const int warp_m = wid >> 2;            // 0..1
    const int warp_n = wid & 3;             // 0..3
    const uint32_t aRow = (uint32_t)(warp_m * 64 + (lane & 15));
    const uint32_t bRow = (uint32_t)(warp_n * 32 + (lane & 7) + ((lane >> 4) & 1) * 8);
    const uint32_t aSel = (uint32_t)((lane >> 4) * 16);
    const uint32_t bSel = (uint32_t)(((lane >> 3) & 1) * 16);
    const int khSkew = (wid & 1) * 2;       // decorrelate LDSM bursts per SMSP

    // producer thread layout (tid 256..383): 1024 chunks/matrix, 8 per thread
    const int pt = tid - 256;
    const uint32_t ldR = (uint32_t)(pt >> 3);
    const uint32_t ldC = (uint32_t)(pt & 7);

    int pst = 0, pph = 1;   // producer cursor
    int cst = 0, cph = 0;   // consumer cursor

    #pragma unroll 1
    for (;;) {
        __syncthreads();                       // prior unit fully drained
        if (tid == 0) *sTile = atomicAdd(&g_tileCtr, 1u);
        __syncthreads();
        const unsigned u = *sTile;
        if (u >= (unsigned)nUnits) break;

        // decode unit -> (band, item, col)
        int blo = 0, bhi = NBANDS;
        while (bhi - blo > 1) {
            const int mid = (blo + bhi) >> 1;
            if ((unsigned)sPref[mid] <= u) blo = mid; else bhi = mid;
        }
        const int band = blo;
        const int rem = (int)u - sPref[band];
        const int it = rem >> 3;               // item within band
        const int col = rem & 7;               // column tile
        const int row0 = band * BM;
        const int col0 = col * BN;

        // find it-th intersecting segment of this band
        int rloI = 0, rhiI = 0;
        const __half* __restrict__ be = g_Bh;
        {
            int cnt = 0;
            #pragma unroll
            for (int s = 0; s < E_SEG; ++s) {
                const int rl = max(sv[s], row0);
                const int rh = min(sv[s + 1], row0 + BM);
                if (rl < rh) {
                    if (cnt == it) {
                        rloI = rl; rhiI = rh;
                        be = g_Bh + (size_t)widx[s] * ((size_t)N_DIM * K_DIM);
                    }
                    ++cnt;
                }
            }
        }

        if (wid >= 8) {
            // ================= PRODUCER WARPS =================
            #pragma unroll 1
            for (int kt = 0; kt < KT; ++kt) {
                mbar_wait(mbE + pst * 8, (uint32_t)pph);
                const uint32_t stg = sb + pst * STAGE_BYTES;
                const int ke = kt * BK + (int)ldC * 8;
                #pragma unroll
                for (int blk = 0; blk < 8; ++blk) {
                    const uint32_t r = ldR + blk * 16;
                    const uint32_t so = swz(r, ldC * 16);
                    cp16(stg + so,                 g_Ahi + (size_t)(row0 + r) * K_DIM + ke);
                    cp16(stg + MAT_BYTES + so,     g_Alo + (size_t)(row0 + r) * K_DIM + ke);
                    cp16(stg + 2 * MAT_BYTES + so, be + (size_t)(col0 + r) * K_DIM + ke);
                }
                cpasync_arrive(mbF + pst * 8);
                if (++pst == NSTAGE) { pst = 0; pph ^= 1; }
            }
        } else {
            // ================= CONSUMER WARPS =================
            float acc[4][4][4];
            #pragma unroll
            for (int i = 0; i < 4; ++i)
                #pragma unroll
                for (int j = 0; j < 4; ++j)
                    #pragma unroll
                    for (int p = 0; p < 4; ++p) acc[i][j][p] = 0.f;

            #pragma unroll 1
            for (int kt = 0; kt < KT; ++kt) {
                mbar_wait(mbF + cst * 8, (uint32_t)cph);

                const uint32_t stg    = sb + cst * STAGE_BYTES;
                const uint32_t stgAhi = stg;
                const uint32_t stgAlo = stg + MAT_BYTES;
                const uint32_t stgBh  = stg + 2 * MAT_BYTES;

                #pragma unroll
                for (int khi = 0; khi < 4; ++khi) {
                    const int kh = (khi + khSkew) & 3;   // phase skew per warp parity
                    const uint32_t aCB = (uint32_t)(kh * 32) + aSel;
                    const uint32_t bCB = (uint32_t)(kh * 32) + bSel;

                    uint32_t ah[4][4], bh[2][4];
                    #pragma unroll
                    for (int mt = 0; mt < 4; ++mt)
                        ldsm4(stgAhi + swz(aRow + mt * 16, aCB), ah[mt]);
                    #pragma unroll
                    for (int p = 0; p < 2; ++p)
                        ldsm4(stgBh + swz(bRow + p * 16, bCB), bh[p]);

                    #pragma unroll
                    for (int mt = 0; mt < 4; ++mt)
                        #pragma unroll
                        for (int nt = 0; nt < 4; ++nt)
                            mma16816(acc[mt][nt], ah[mt],
                                     bh[nt >> 1][(nt & 1) * 2], bh[nt >> 1][(nt & 1) * 2 + 1]);

                    uint32_t al[4][4];
                    #pragma unroll
                    for (int mt = 0; mt < 4; ++mt)
                        ldsm4(stgAlo + swz(aRow + mt * 16, aCB), al[mt]);

                    #pragma unroll
                    for (int mt = 0; mt < 4; ++mt)
                        #pragma unroll
                        for (int nt = 0; nt < 4; ++nt)
                            mma16816(acc[mt][nt], al[mt],
                                     bh[nt >> 1][(nt & 1) * 2], bh[nt >> 1][(nt & 1) * 2 + 1]);
                }

                if (lane == 0) mbar_arrive(mbE + cst * 8);
                if (++cst == NSTAGE) { cst = 0; cph ^= 1; }
            }

            // epilogue: masked rows for this unit's segment
            {
                const int cbase = col0 + warp_n * 32 + (lane & 3) * 2;
                #pragma unroll
                for (int mt = 0; mt < 4; ++mt) {
                    const int r0 = row0 + warp_m * 64 + mt * 16 + (lane >> 2);
                    const int r1 = r0 + 8;
                    const bool w0 = (r0 >= rloI && r0 < rhiI);
                    const bool w1 = (r1 >= rloI && r1 < rhiI);
                    #pragma unroll
                    for (int nt = 0; nt < 4; ++nt) {
                        const int cc = cbase + nt * 8;
                        if (w0) *(float2*)&C[(size_t)r0 * N_DIM + cc] =
                                    make_float2(acc[mt][nt][0], acc[mt][nt][1]);
                        if (w1) *(float2*)&C[(size_t)r1 * N_DIM + cc] =
                                    make_float2(acc[mt][nt][2], acc[mt][nt][3]);
                    }
                }
            }
        }
    }
}

extern "C" void kernel_launch(void* const* d_in, const int* in_sizes, int n_in,
                              void* d_out, int out_size)
{
    const float* a = (const float*)d_in[0];    // [M, K]
    const float* b = (const float*)d_in[1];    // [E, N, K]
    const int* seg = nullptr;
    const int* widx = nullptr;
    for (int i = 0; i < n_in; ++i) {
        if (in_sizes[i] == E_SEG + 1)  seg  = (const int*)d_in[i];
        else if (in_sizes[i] == E_SEG) widx = (const int*)d_in[i];
    }
    float* c = (float*)d_out;

    split_AB<<<(NA4 + NB4) / 256, 256>>>((const float4*)a, (const float4*)b);

    cudaFuncSetAttribute(grouped_gemm_hmma,
                         cudaFuncAttributeMaxDynamicSharedMemorySize, SMEM_TOTAL);
    grouped_gemm_hmma<<<GRID_P, THREADS, SMEM_TOTAL>>>(seg, widx, c);
}